// round 5
// baseline (speedup 1.0000x reference)
#include <cuda_runtime.h>
#include <math_constants.h>

#define DIM    2048
#define NB     16
#define LCTX   4096
#define NSPLIT 64
#define ROWS   (LCTX/NSPLIT)   /* 64 rows per attention split */
#define RPI    4               /* rows per inner iteration    */
#define ISPLIT 16
#define ICHUNK (DIM/ISPLIT)    /* 128 */
#define SCALE  0.02209708691207961f /* 1/sqrt(2048) */

/* -------- scratch ( __device__ globals, no allocation ) -------- */
__device__ float g_q   [NB*DIM];
__device__ float g_qk  [NB*DIM];
__device__ float g_part[ISPLIT*NB*DIM];      /* reused by both GEMVs */
__device__ float g_m   [NB*NSPLIT];
__device__ float g_s   [NB*NSPLIT];
__device__ float g_c   [(size_t)NB*NSPLIT*DIM];
__device__ float g_cn  [NB*DIM];

/* ---------------------------------------------------------------
 * GEMV partial:  part[isplit][b][o] = sum_{i in chunk} A[b][i]*W[i][o]
 * grid (DIM/128, ISPLIT), block 128.  A is [NB][DIM], W is [DIM][DIM].
 * --------------------------------------------------------------- */
__global__ void __launch_bounds__(128) gemv_partial_k(
    const float* __restrict__ A, const float* __restrict__ W,
    float* __restrict__ part)
{
    __shared__ float As[NB*ICHUNK];           /* 8 KB */
    const int o  = blockIdx.x*128 + threadIdx.x;
    const int i0 = blockIdx.y*ICHUNK;

    for (int idx = threadIdx.x; idx < NB*ICHUNK; idx += 128) {
        int bb = idx >> 7, ii = idx & (ICHUNK-1);
        As[idx] = A[bb*DIM + i0 + ii];
    }
    __syncthreads();

    float acc[NB];
#pragma unroll
    for (int b = 0; b < NB; b++) acc[b] = 0.f;

    const float* Wp = W + (size_t)i0*DIM + o;
#pragma unroll 4
    for (int ii = 0; ii < ICHUNK; ii++) {
        float w = Wp[(size_t)ii*DIM];
#pragma unroll
        for (int b = 0; b < NB; b++)
            acc[b] = fmaf(As[b*ICHUNK + ii], w, acc[b]);
    }

    float* pp = part + ((size_t)blockIdx.y*NB)*DIM + o;
#pragma unroll
    for (int b = 0; b < NB; b++) pp[(size_t)b*DIM] = acc[b];
}

/* reduce ISPLIT partials + bias.  grid NB*DIM/256, block 256 */
__global__ void __launch_bounds__(256) reduce_bias_k(
    const float* __restrict__ part, const float* __restrict__ bias,
    float* __restrict__ out)
{
    int idx = blockIdx.x*256 + threadIdx.x;   /* = b*DIM + o */
    int o   = idx & (DIM-1);
    float s = bias[o];
#pragma unroll
    for (int k = 0; k < ISPLIT; k++) s += part[(size_t)k*NB*DIM + idx];
    out[idx] = s;
}

/* ---------------------------------------------------------------
 * qk[b][i] = SCALE * sum_a q[b][a] * Wk[i][a]
 * grid DIM/8 blocks, block 256 (8 warps, warp w -> row i)
 * --------------------------------------------------------------- */
__global__ void __launch_bounds__(256) qk_kernel(
    const float* __restrict__ q, const float* __restrict__ Wk,
    float* __restrict__ qk)
{
    __shared__ float qs[NB*ICHUNK];           /* 8 KB staged q chunk */
    const int warp = threadIdx.x >> 5, lane = threadIdx.x & 31;
    const int i = blockIdx.x*8 + warp;

    float acc[NB];
#pragma unroll
    for (int b = 0; b < NB; b++) acc[b] = 0.f;

    for (int a0 = 0; a0 < DIM; a0 += ICHUNK) {
        __syncthreads();
        for (int idx = threadIdx.x; idx < NB*ICHUNK; idx += 256) {
            int bb = idx >> 7, aa = idx & (ICHUNK-1);
            qs[idx] = q[bb*DIM + a0 + aa];
        }
        __syncthreads();
        const float* wrow = Wk + (size_t)i*DIM + a0;
        for (int aa = lane; aa < ICHUNK; aa += 32) {
            float wv = wrow[aa];
#pragma unroll
            for (int b = 0; b < NB; b++)
                acc[b] = fmaf(qs[b*ICHUNK + aa], wv, acc[b]);
        }
    }
#pragma unroll
    for (int b = 0; b < NB; b++) {
#pragma unroll
        for (int off = 16; off; off >>= 1)
            acc[b] += __shfl_xor_sync(0xffffffffu, acc[b], off);
    }
    if (lane == 0) {
#pragma unroll
        for (int b = 0; b < NB; b++) qk[b*DIM + i] = acc[b]*SCALE;
    }
}

/* ---------------------------------------------------------------
 * Main streaming kernel: online softmax + weighted context accum.
 * grid (NSPLIT, NB), block 256.  Thread t owns columns 8t..8t+7.
 * Emits partial (m, s, c[DIM]) per (b, split).
 * --------------------------------------------------------------- */
__device__ __forceinline__ float dot8(float4 a0, float4 a1, float4 b0, float4 b1)
{
    float d = a0.x*b0.x;
    d = fmaf(a0.y, b0.y, d); d = fmaf(a0.z, b0.z, d); d = fmaf(a0.w, b0.w, d);
    d = fmaf(a1.x, b1.x, d); d = fmaf(a1.y, b1.y, d);
    d = fmaf(a1.z, b1.z, d); d = fmaf(a1.w, b1.w, d);
    return d;
}

__global__ void __launch_bounds__(256) attn_partial_k(
    const float* __restrict__ ctx, const float* __restrict__ qk,
    float* __restrict__ mp, float* __restrict__ sp, float* __restrict__ cp)
{
    const int b = blockIdx.y, split = blockIdx.x;
    const int t = threadIdx.x;
    const int warp = t >> 5, lane = t & 31;

    const float4* xb = (const float4*)(ctx + ((size_t)b*LCTX + (size_t)split*ROWS)*DIM);
    const float4* qv = (const float4*)(qk + (size_t)b*DIM);
    const float4 qv0 = qv[2*t], qv1 = qv[2*t+1];

    float4 c0 = make_float4(0,0,0,0), c1 = make_float4(0,0,0,0);
    float  m = -CUDART_INF_F, ssum = 0.f;

    __shared__ float red[RPI][8];

    for (int r0 = 0; r0 < ROWS; r0 += RPI) {
        float4 xr0[RPI], xr1[RPI];
        float  dot[RPI];
#pragma unroll
        for (int r = 0; r < RPI; r++) {
            const float4* row = xb + (size_t)(r0 + r)*(DIM/4);
            xr0[r] = row[2*t];
            xr1[r] = row[2*t+1];
            dot[r] = dot8(xr0[r], xr1[r], qv0, qv1);
        }
#pragma unroll
        for (int r = 0; r < RPI; r++) {
#pragma unroll
            for (int off = 16; off; off >>= 1)
                dot[r] += __shfl_xor_sync(0xffffffffu, dot[r], off);
        }
        if (lane == 0) {
#pragma unroll
            for (int r = 0; r < RPI; r++) red[r][warp] = dot[r];
        }
        __syncthreads();
        float sc[RPI];
#pragma unroll
        for (int r = 0; r < RPI; r++) {
            float v = 0.f;
#pragma unroll
            for (int w = 0; w < 8; w++) v += red[r][w];
            sc[r] = v;
        }
        __syncthreads();

        float mnew = m;
#pragma unroll
        for (int r = 0; r < RPI; r++) mnew = fmaxf(mnew, sc[r]);
        float f = __expf(m - mnew);       /* first iter: exp(-inf)=0 */
        ssum *= f;
        c0.x *= f; c0.y *= f; c0.z *= f; c0.w *= f;
        c1.x *= f; c1.y *= f; c1.z *= f; c1.w *= f;
#pragma unroll
        for (int r = 0; r < RPI; r++) {
            float w = __expf(sc[r] - mnew);
            ssum += w;
            c0.x = fmaf(w, xr0[r].x, c0.x); c0.y = fmaf(w, xr0[r].y, c0.y);
            c0.z = fmaf(w, xr0[r].z, c0.z); c0.w = fmaf(w, xr0[r].w, c0.w);
            c1.x = fmaf(w, xr1[r].x, c1.x); c1.y = fmaf(w, xr1[r].y, c1.y);
            c1.z = fmaf(w, xr1[r].z, c1.z); c1.w = fmaf(w, xr1[r].w, c1.w);
        }
        m = mnew;
    }

    const int pidx = b*NSPLIT + split;
    if (t == 0) { mp[pidx] = m; sp[pidx] = ssum; }
    float4* cpp = (float4*)(cp + (size_t)pidx*DIM);
    cpp[2*t] = c0; cpp[2*t+1] = c1;
}

/* ---------------------------------------------------------------
 * Combine split partials:  cn[b][col] = (1/S) * sum_j exp(m_j-M)*c_j[col]
 * grid (NB, 8), block 256 (one column per thread).
 * --------------------------------------------------------------- */
__global__ void __launch_bounds__(256) combine_k(
    const float* __restrict__ mp, const float* __restrict__ sp,
    const float* __restrict__ cp, float* __restrict__ cn)
{
    const int b = blockIdx.x;
    const int t = threadIdx.x;
    __shared__ float fsh[NSPLIT];
    __shared__ float invS_sh;

    float M = -CUDART_INF_F;
    for (int j = 0; j < NSPLIT; j++) M = fmaxf(M, mp[b*NSPLIT + j]);
    if (t < NSPLIT) fsh[t] = __expf(mp[b*NSPLIT + t] - M);
    __syncthreads();
    if (t == 0) {
        float S = 0.f;
        for (int j = 0; j < NSPLIT; j++) S += sp[b*NSPLIT + j]*fsh[j];
        invS_sh = 1.f/S;
    }
    __syncthreads();
    const float invS = invS_sh;

    const int col = blockIdx.y*256 + t;
    float acc = 0.f;
    for (int j = 0; j < NSPLIT; j++)
        acc += cp[((size_t)(b*NSPLIT + j))*DIM + col]*fsh[j];
    cn[b*DIM + col] = acc*invS;
}

/* ---------------------------------------------------------------- */
extern "C" void kernel_launch(void* const* d_in, const int* in_sizes, int n_in,
                              void* d_out, int out_size)
{
    const float* cur = (const float*)d_in[0];
    const float* ctx = (const float*)d_in[1];
    const float* Wq  = (const float*)d_in[2];
    const float* bq  = (const float*)d_in[3];
    const float* Wk  = (const float*)d_in[4];
    /* bk (d_in[5]) is provably softmax-invariant: q.bk is constant in l */
    const float* Wv  = (const float*)d_in[6];
    const float* bv  = (const float*)d_in[7];
    float* out = (float*)d_out;

    float *q, *qkv, *part, *mP, *sP, *cP, *cn;
    cudaGetSymbolAddress((void**)&q,    g_q);
    cudaGetSymbolAddress((void**)&qkv,  g_qk);
    cudaGetSymbolAddress((void**)&part, g_part);
    cudaGetSymbolAddress((void**)&mP,   g_m);
    cudaGetSymbolAddress((void**)&sP,   g_s);
    cudaGetSymbolAddress((void**)&cP,   g_c);
    cudaGetSymbolAddress((void**)&cn,   g_cn);

    /* 1-2: q = cur @ Wq + bq */
    gemv_partial_k<<<dim3(DIM/128, ISPLIT), 128>>>(cur, Wq, part);
    reduce_bias_k<<<NB*DIM/256, 256>>>(part, bq, q);

    /* 3: qk = SCALE * (q @ Wk^T) */
    qk_kernel<<<DIM/8, 256>>>(q, Wk, qkv);

    /* 4: streaming online-softmax over context, split partials */
    attn_partial_k<<<dim3(NSPLIT, NB), 256>>>(ctx, qkv, mP, sP, cP);

    /* 5: combine partials -> normalized weighted context cn */
    combine_k<<<dim3(NB, DIM/256), 256>>>(mP, sP, cP, cn);

    /* 6-7: out = cn @ Wv + bv */
    gemv_partial_k<<<dim3(DIM/128, ISPLIT), 128>>>(cn, Wv, part);
    reduce_bias_k<<<NB*DIM/256, 256>>>(part, bv, out);
}

// round 6
// speedup vs baseline: 1.0314x; 1.0314x over previous
#include <cuda_runtime.h>
#include <math_constants.h>

#define DIM    2048
#define NB     16
#define LCTX   4096
#define NSPLIT 64
#define ROWS   (LCTX/NSPLIT)   /* 64 rows per attention split */
#define RPI    4               /* rows per inner iteration    */
#define ISPLIT 32
#define ICHUNK (DIM/ISPLIT)    /* 64 */
#define ASPLIT 4
#define ACH    (DIM/ASPLIT)    /* 512 */
#define SCALE  0.02209708691207961f /* 1/sqrt(2048) */

/* -------- scratch ( __device__ globals, no allocation ) -------- */
__device__ float g_q   [NB*DIM];
__device__ float g_qk  [NB*DIM];
__device__ float g_part[ISPLIT*NB*DIM];      /* reused: gemv partials + qk partials */
__device__ float g_m   [NB*NSPLIT];
__device__ float g_s   [NB*NSPLIT];
__device__ float g_c   [(size_t)NB*NSPLIT*DIM];
__device__ float g_cn  [NB*DIM];

/* ---------------------------------------------------------------
 * GEMV partial:  part[isplit][b][o] = sum_{i in chunk} A[b][i]*W[i][o]
 * grid (DIM/128, ISPLIT), block 128.
 * --------------------------------------------------------------- */
__global__ void __launch_bounds__(128) gemv_partial_k(
    const float* __restrict__ A, const float* __restrict__ W,
    float* __restrict__ part)
{
    __shared__ float As[NB*ICHUNK];           /* 4 KB */
    const int o  = blockIdx.x*128 + threadIdx.x;
    const int i0 = blockIdx.y*ICHUNK;

    for (int idx = threadIdx.x; idx < NB*ICHUNK; idx += 128) {
        int bb = idx / ICHUNK, ii = idx & (ICHUNK-1);
        As[idx] = A[bb*DIM + i0 + ii];
    }
    __syncthreads();

    float acc[NB];
#pragma unroll
    for (int b = 0; b < NB; b++) acc[b] = 0.f;

    const float* Wp = W + (size_t)i0*DIM + o;
#pragma unroll 8
    for (int ii = 0; ii < ICHUNK; ii++) {
        float w = Wp[(size_t)ii*DIM];
#pragma unroll
        for (int b = 0; b < NB; b++)
            acc[b] = fmaf(As[b*ICHUNK + ii], w, acc[b]);
    }

    float* pp = part + ((size_t)blockIdx.y*NB)*DIM + o;
#pragma unroll
    for (int b = 0; b < NB; b++) pp[(size_t)b*DIM] = acc[b];
}

/* reduce ISPLIT partials + bias.  grid NB*DIM/256, block 256 */
__global__ void __launch_bounds__(256) reduce_bias_k(
    const float* __restrict__ part, const float* __restrict__ bias,
    float* __restrict__ out)
{
    int idx = blockIdx.x*256 + threadIdx.x;   /* = b*DIM + o */
    int o   = idx & (DIM-1);
    float s = bias[o];
#pragma unroll
    for (int k = 0; k < ISPLIT; k++) s += part[(size_t)k*NB*DIM + idx];
    out[idx] = s;
}

/* ---------------------------------------------------------------
 * qk partial over a-chunks:
 *   part[j][b][i] = sum_{a in chunk j} q[b][a] * Wk[i][a]
 * grid (DIM/8, ASPLIT), block 256 (warp w -> row i).
 * --------------------------------------------------------------- */
__global__ void __launch_bounds__(256) qk_partial_k(
    const float* __restrict__ q, const float* __restrict__ Wk,
    float* __restrict__ part)
{
    __shared__ float qs[NB*128];              /* 8 KB staged q chunk */
    const int warp = threadIdx.x >> 5, lane = threadIdx.x & 31;
    const int i = blockIdx.x*8 + warp;
    const int ab = blockIdx.y*ACH;

    float acc[NB];
#pragma unroll
    for (int b = 0; b < NB; b++) acc[b] = 0.f;

    for (int a0 = ab; a0 < ab + ACH; a0 += 128) {
        __syncthreads();
        for (int idx = threadIdx.x; idx < NB*128; idx += 256) {
            int bb = idx >> 7, aa = idx & 127;
            qs[idx] = q[bb*DIM + a0 + aa];
        }
        __syncthreads();
        const float* wrow = Wk + (size_t)i*DIM + a0;
#pragma unroll
        for (int aa = lane; aa < 128; aa += 32) {
            float wv = wrow[aa];
#pragma unroll
            for (int b = 0; b < NB; b++)
                acc[b] = fmaf(qs[b*128 + aa], wv, acc[b]);
        }
    }
#pragma unroll
    for (int b = 0; b < NB; b++) {
#pragma unroll
        for (int off = 16; off; off >>= 1)
            acc[b] += __shfl_xor_sync(0xffffffffu, acc[b], off);
    }
    if (lane == 0) {
#pragma unroll
        for (int b = 0; b < NB; b++)
            part[((size_t)(blockIdx.y*NB + b))*DIM + i] = acc[b];
    }
}

/* qk reduce + scale.  grid NB*DIM/256, block 256 */
__global__ void __launch_bounds__(256) qk_reduce_k(
    const float* __restrict__ part, float* __restrict__ qk)
{
    int idx = blockIdx.x*256 + threadIdx.x;
    float s = 0.f;
#pragma unroll
    for (int j = 0; j < ASPLIT; j++) s += part[(size_t)j*NB*DIM + idx];
    qk[idx] = s*SCALE;
}

/* ---------------------------------------------------------------
 * Main streaming kernel: online softmax + weighted context accum.
 * grid (NSPLIT, NB), block 256, rows staged through a 32KB smem
 * tile (low reg pressure -> 6 blocks/SM).  Thread t owns columns
 * {4t..4t+3} and {1024+4t..1024+4t+3}  (lane-contiguous LDS.128).
 * --------------------------------------------------------------- */
__device__ __forceinline__ float dot8(float4 a0, float4 a1, float4 b0, float4 b1)
{
    float d = a0.x*b0.x;
    d = fmaf(a0.y, b0.y, d); d = fmaf(a0.z, b0.z, d); d = fmaf(a0.w, b0.w, d);
    d = fmaf(a1.x, b1.x, d); d = fmaf(a1.y, b1.y, d);
    d = fmaf(a1.z, b1.z, d); d = fmaf(a1.w, b1.w, d);
    return d;
}

__global__ void __launch_bounds__(256, 6) attn_partial_k(
    const float* __restrict__ ctx, const float* __restrict__ qk,
    float* __restrict__ mp, float* __restrict__ sp, float* __restrict__ cp)
{
    const int b = blockIdx.y, split = blockIdx.x;
    const int t = threadIdx.x;
    const int warp = t >> 5, lane = t & 31;

    __shared__ float4 xs[RPI][DIM/4];         /* 32 KB row tile */
    __shared__ float  red[RPI][8];

    const float4* xb = (const float4*)(ctx + ((size_t)b*LCTX + (size_t)split*ROWS)*DIM);
    const float4* qv = (const float4*)(qk + (size_t)b*DIM);
    const float4 qv0 = qv[t], qv1 = qv[t + 256];

    float4 c0 = make_float4(0,0,0,0), c1 = make_float4(0,0,0,0);
    float  m = -CUDART_INF_F, ssum = 0.f;

    for (int r0 = 0; r0 < ROWS; r0 += RPI) {
        /* stage RPI rows: 2048 float4, 8 per thread, coalesced */
#pragma unroll
        for (int k = 0; k < 2*RPI; k++) {
            int idx = k*256 + t;
            int r = idx >> 9, c = idx & 511;
            xs[r][c] = xb[(size_t)(r0 + r)*(DIM/4) + c];
        }
        __syncthreads();

        float dot[RPI];
#pragma unroll
        for (int r = 0; r < RPI; r++)
            dot[r] = dot8(xs[r][t], xs[r][t + 256], qv0, qv1);
#pragma unroll
        for (int r = 0; r < RPI; r++) {
#pragma unroll
            for (int off = 16; off; off >>= 1)
                dot[r] += __shfl_xor_sync(0xffffffffu, dot[r], off);
        }
        if (lane == 0) {
#pragma unroll
            for (int r = 0; r < RPI; r++) red[r][warp] = dot[r];
        }
        __syncthreads();

        float sc[RPI], mnew = m;
#pragma unroll
        for (int r = 0; r < RPI; r++) {
            float v = red[r][0] + red[r][1] + red[r][2] + red[r][3]
                    + red[r][4] + red[r][5] + red[r][6] + red[r][7];
            sc[r] = v;
            mnew = fmaxf(mnew, v);
        }

        float f = __expf(m - mnew);           /* first iter: exp(-inf)=0 */
        ssum *= f;
        c0.x *= f; c0.y *= f; c0.z *= f; c0.w *= f;
        c1.x *= f; c1.y *= f; c1.z *= f; c1.w *= f;
#pragma unroll
        for (int r = 0; r < RPI; r++) {
            float w = __expf(sc[r] - mnew);
            ssum += w;
            float4 a0 = xs[r][t], a1 = xs[r][t + 256];
            c0.x = fmaf(w, a0.x, c0.x); c0.y = fmaf(w, a0.y, c0.y);
            c0.z = fmaf(w, a0.z, c0.z); c0.w = fmaf(w, a0.w, c0.w);
            c1.x = fmaf(w, a1.x, c1.x); c1.y = fmaf(w, a1.y, c1.y);
            c1.z = fmaf(w, a1.z, c1.z); c1.w = fmaf(w, a1.w, c1.w);
        }
        m = mnew;
        __syncthreads();                      /* protect xs/red for next batch */
    }

    const int pidx = b*NSPLIT + split;
    if (t == 0) { mp[pidx] = m; sp[pidx] = ssum; }
    float4* cpp = (float4*)(cp + (size_t)pidx*DIM);
    cpp[t] = c0; cpp[t + 256] = c1;           /* matches owned-column layout */
}

/* ---------------------------------------------------------------
 * Combine split partials:  cn[b][col] = (1/S) * sum_j exp(m_j-M)*c_j[col]
 * grid (NB, DIM/128), block 128.
 * --------------------------------------------------------------- */
__global__ void __launch_bounds__(128) combine_k(
    const float* __restrict__ mp, const float* __restrict__ sp,
    const float* __restrict__ cp, float* __restrict__ cn)
{
    const int b = blockIdx.x;
    const int t = threadIdx.x;
    __shared__ float fsh[NSPLIT];
    __shared__ float invS_sh;

    float M = -CUDART_INF_F;
#pragma unroll
    for (int j = 0; j < NSPLIT; j++) M = fmaxf(M, mp[b*NSPLIT + j]);
    if (t < NSPLIT) fsh[t] = __expf(mp[b*NSPLIT + t] - M);
    __syncthreads();
    if (t == 0) {
        float S = 0.f;
#pragma unroll
        for (int j = 0; j < NSPLIT; j++) S += sp[b*NSPLIT + j]*fsh[j];
        invS_sh = 1.f/S;
    }
    __syncthreads();
    const float invS = invS_sh;

    const int col = blockIdx.y*128 + t;
    float acc = 0.f;
#pragma unroll 4
    for (int j = 0; j < NSPLIT; j++)
        acc += cp[((size_t)(b*NSPLIT + j))*DIM + col]*fsh[j];
    cn[b*DIM + col] = acc*invS;
}

/* ---------------------------------------------------------------- */
extern "C" void kernel_launch(void* const* d_in, const int* in_sizes, int n_in,
                              void* d_out, int out_size)
{
    const float* cur = (const float*)d_in[0];
    const float* ctx = (const float*)d_in[1];
    const float* Wq  = (const float*)d_in[2];
    const float* bq  = (const float*)d_in[3];
    const float* Wk  = (const float*)d_in[4];
    /* bk (d_in[5]) is provably softmax-invariant: q.bk is constant in l */
    const float* Wv  = (const float*)d_in[6];
    const float* bv  = (const float*)d_in[7];
    float* out = (float*)d_out;

    float *q, *qkv, *part, *mP, *sP, *cP, *cn;
    cudaGetSymbolAddress((void**)&q,    g_q);
    cudaGetSymbolAddress((void**)&qkv,  g_qk);
    cudaGetSymbolAddress((void**)&part, g_part);
    cudaGetSymbolAddress((void**)&mP,   g_m);
    cudaGetSymbolAddress((void**)&sP,   g_s);
    cudaGetSymbolAddress((void**)&cP,   g_c);
    cudaGetSymbolAddress((void**)&cn,   g_cn);

    /* 1-2: q = cur @ Wq + bq */
    gemv_partial_k<<<dim3(DIM/128, ISPLIT), 128>>>(cur, Wq, part);
    reduce_bias_k<<<NB*DIM/256, 256>>>(part, bq, q);

    /* 3-4: qk = SCALE * (q @ Wk^T), a-split for parallelism */
    qk_partial_k<<<dim3(DIM/8, ASPLIT), 256>>>(q, Wk, part);
    qk_reduce_k<<<NB*DIM/256, 256>>>(part, qkv);

    /* 5: streaming online-softmax over context, split partials */
    attn_partial_k<<<dim3(NSPLIT, NB), 256>>>(ctx, qkv, mP, sP, cP);

    /* 6: combine partials -> normalized weighted context cn */
    combine_k<<<dim3(NB, DIM/128), 128>>>(mP, sP, cP, cn);

    /* 7-8: out = cn @ Wv + bv */
    gemv_partial_k<<<dim3(DIM/128, ISPLIT), 128>>>(cn, Wv, part);
    reduce_bias_k<<<NB*DIM/256, 256>>>(part, bv, out);
}

// round 10
// speedup vs baseline: 1.2704x; 1.2317x over previous
#include <cuda_runtime.h>
#include <math_constants.h>

#define DIM    2048
#define NB     16
#define LCTX   4096
#define NSPLIT 64
#define ROWS   (LCTX/NSPLIT)   /* 64 rows per attention split   */
#define RPI    4               /* rows per pipelined tile       */
#define NT     (ROWS/RPI)      /* 16 tiles per block            */
#define ISPLIT 32
#define ICHUNK (DIM/ISPLIT)    /* 64 */
#define ASPLIT 4
#define ACH    (DIM/ASPLIT)    /* 512 */
#define SCALE  0.02209708691207961f /* 1/sqrt(2048) */

/* -------- scratch ( __device__ globals, no allocation ) -------- */
__device__ float g_q   [NB*DIM];
__device__ float g_part[ISPLIT*NB*DIM];      /* reused: gemv partials + qk partials */
__device__ float g_m   [NB*NSPLIT];
__device__ float g_s   [NB*NSPLIT];
__device__ float g_c   [(size_t)NB*NSPLIT*DIM];
__device__ float g_cn  [NB*DIM];

/* ---------------- cp.async helpers ---------------- */
__device__ __forceinline__ void cpa16(void* smem_dst, const void* gsrc)
{
    unsigned saddr = (unsigned)__cvta_generic_to_shared(smem_dst);
    asm volatile("cp.async.cg.shared.global [%0], [%1], 16;\n"
                 :: "r"(saddr), "l"(gsrc));
}
__device__ __forceinline__ void cpa_commit()
{ asm volatile("cp.async.commit_group;\n"); }
__device__ __forceinline__ void cpa_wait0()
{ asm volatile("cp.async.wait_group 0;\n"); }

/* ---------------------------------------------------------------
 * GEMV partial:  part[isplit][b][o] = sum_{i in chunk} A[b][i]*W[i][o]
 * grid (DIM/128, ISPLIT), block 128.
 * --------------------------------------------------------------- */
__global__ void __launch_bounds__(128) gemv_partial_k(
    const float* __restrict__ A, const float* __restrict__ W,
    float* __restrict__ part)
{
    __shared__ float As[NB*ICHUNK];           /* 4 KB */
    const int o  = blockIdx.x*128 + threadIdx.x;
    const int i0 = blockIdx.y*ICHUNK;

    for (int idx = threadIdx.x; idx < NB*ICHUNK; idx += 128) {
        int bb = idx / ICHUNK, ii = idx & (ICHUNK-1);
        As[idx] = A[bb*DIM + i0 + ii];
    }
    __syncthreads();

    float acc[NB];
#pragma unroll
    for (int b = 0; b < NB; b++) acc[b] = 0.f;

    const float* Wp = W + (size_t)i0*DIM + o;
#pragma unroll 16
    for (int ii = 0; ii < ICHUNK; ii++) {
        float w = Wp[(size_t)ii*DIM];
#pragma unroll
        for (int b = 0; b < NB; b++)
            acc[b] = fmaf(As[b*ICHUNK + ii], w, acc[b]);
    }

    float* pp = part + ((size_t)blockIdx.y*NB)*DIM + o;
#pragma unroll
    for (int b = 0; b < NB; b++) pp[(size_t)b*DIM] = acc[b];
}

/* reduce ISPLIT partials + bias.  grid NB*DIM/256, block 256 */
__global__ void __launch_bounds__(256) reduce_bias_k(
    const float* __restrict__ part, const float* __restrict__ bias,
    float* __restrict__ out)
{
    int idx = blockIdx.x*256 + threadIdx.x;   /* = b*DIM + o */
    int o   = idx & (DIM-1);
    float s = bias[o];
#pragma unroll
    for (int k = 0; k < ISPLIT; k++) s += part[(size_t)k*NB*DIM + idx];
    out[idx] = s;
}

/* ---------------------------------------------------------------
 * qk partial over a-chunks (UNscaled; attn prologue fuses the
 * 4-way reduce + SCALE):
 *   part[j][b][i] = sum_{a in chunk j} q[b][a] * Wk[i][a]
 * grid (DIM/8, ASPLIT), block 256 (warp w -> row i).
 * --------------------------------------------------------------- */
__global__ void __launch_bounds__(256) qk_partial_k(
    const float* __restrict__ q, const float* __restrict__ Wk,
    float* __restrict__ part)
{
    __shared__ float qs[NB*128];              /* 8 KB staged q chunk */
    const int warp = threadIdx.x >> 5, lane = threadIdx.x & 31;
    const int i = blockIdx.x*8 + warp;
    const int ab = blockIdx.y*ACH;

    float acc[NB];
#pragma unroll
    for (int b = 0; b < NB; b++) acc[b] = 0.f;

    for (int a0 = ab; a0 < ab + ACH; a0 += 128) {
        __syncthreads();
        for (int idx = threadIdx.x; idx < NB*128; idx += 256) {
            int bb = idx >> 7, aa = idx & 127;
            qs[idx] = q[bb*DIM + a0 + aa];
        }
        __syncthreads();
        const float* wrow = Wk + (size_t)i*DIM + a0;
#pragma unroll
        for (int aa = lane; aa < 128; aa += 32) {
            float wv = wrow[aa];
#pragma unroll
            for (int b = 0; b < NB; b++)
                acc[b] = fmaf(qs[b*128 + aa], wv, acc[b]);
        }
    }
#pragma unroll
    for (int b = 0; b < NB; b++) {
#pragma unroll
        for (int off = 16; off; off >>= 1)
            acc[b] += __shfl_xor_sync(0xffffffffu, acc[b], off);
    }
    if (lane == 0) {
#pragma unroll
        for (int b = 0; b < NB; b++)
            part[((size_t)(blockIdx.y*NB + b))*DIM + i] = acc[b];
    }
}

/* ---------------------------------------------------------------
 * Main streaming kernel: online softmax + weighted context accum,
 * double-buffered cp.async pipeline so a 32KB tile is always in
 * flight while the previous one is being consumed.
 * grid (NSPLIT, NB), block 256, 64KB dynamic smem (2 x RPI rows).
 * Thread t owns columns {4t..4t+3} and {1024+4t..1024+4t+3}.
 * Prologue fuses the qk 4-partial reduce + SCALE.
 * --------------------------------------------------------------- */
__device__ __forceinline__ float dot8(float4 a0, float4 a1, float4 b0, float4 b1)
{
    float d = a0.x*b0.x;
    d = fmaf(a0.y, b0.y, d); d = fmaf(a0.z, b0.z, d); d = fmaf(a0.w, b0.w, d);
    d = fmaf(a1.x, b1.x, d); d = fmaf(a1.y, b1.y, d);
    d = fmaf(a1.z, b1.z, d); d = fmaf(a1.w, b1.w, d);
    return d;
}

__global__ void __launch_bounds__(256) attn_partial_k(
    const float* __restrict__ ctx, const float* __restrict__ qkpart,
    float* __restrict__ mp, float* __restrict__ sp, float* __restrict__ cp)
{
    extern __shared__ float4 xs[];            /* [2][RPI][DIM/4] = 64 KB */
    __shared__ float red[RPI][8];

    const int b = blockIdx.y, split = blockIdx.x;
    const int t = threadIdx.x;
    const int warp = t >> 5, lane = t & 31;

    const float4* xb = (const float4*)(ctx + ((size_t)b*LCTX + (size_t)split*ROWS)*DIM);

    /* fused qk reduce + scale: qv[col] = SCALE * sum_j part[j][b][col] */
    const float4* pv = (const float4*)qkpart;
    const size_t boff = (size_t)b*(DIM/4);
    float4 qv0, qv1;
    {
        float4 s0 = pv[boff + t],                     s1 = pv[boff + t + 256];
        float4 u0 = pv[(size_t)NB*(DIM/4)   + boff + t], u1 = pv[(size_t)NB*(DIM/4)   + boff + t + 256];
        float4 v0 = pv[(size_t)2*NB*(DIM/4) + boff + t], v1 = pv[(size_t)2*NB*(DIM/4) + boff + t + 256];
        float4 w0 = pv[(size_t)3*NB*(DIM/4) + boff + t], w1 = pv[(size_t)3*NB*(DIM/4) + boff + t + 256];
        qv0.x = SCALE*(s0.x+u0.x+v0.x+w0.x); qv0.y = SCALE*(s0.y+u0.y+v0.y+w0.y);
        qv0.z = SCALE*(s0.z+u0.z+v0.z+w0.z); qv0.w = SCALE*(s0.w+u0.w+v0.w+w0.w);
        qv1.x = SCALE*(s1.x+u1.x+v1.x+w1.x); qv1.y = SCALE*(s1.y+u1.y+v1.y+w1.y);
        qv1.z = SCALE*(s1.z+u1.z+v1.z+w1.z); qv1.w = SCALE*(s1.w+u1.w+v1.w+w1.w);
    }

    float4 c0 = make_float4(0,0,0,0), c1 = make_float4(0,0,0,0);
    float  m = -CUDART_INF_F, ssum = 0.f;

    /* prologue: stage tile 0 into buffer 0 (2048 float4, 8/thread) */
#pragma unroll
    for (int k = 0; k < 2*RPI; k++) {
        int idx = k*256 + t;
        cpa16(&xs[idx], &xb[idx]);
    }
    cpa_commit();

    for (int tile = 0; tile < NT; tile++) {
        float4* cur = xs + ((tile & 1) ? RPI*(DIM/4) : 0);
        float4* nxt = xs + ((tile & 1) ? 0 : RPI*(DIM/4));

        cpa_wait0();          /* tile data landed                */
        __syncthreads();      /* ..and prev consumers done w/cur */

        /* prefetch next tile while we compute on this one */
        if (tile + 1 < NT) {
            const float4* src = xb + (size_t)(tile + 1)*RPI*(DIM/4);
#pragma unroll
            for (int k = 0; k < 2*RPI; k++) {
                int idx = k*256 + t;
                cpa16(&nxt[idx], &src[idx]);
            }
        }
        cpa_commit();

        /* scores */
        float dot[RPI];
#pragma unroll
        for (int r = 0; r < RPI; r++)
            dot[r] = dot8(cur[r*(DIM/4) + t], cur[r*(DIM/4) + t + 256], qv0, qv1);
#pragma unroll
        for (int r = 0; r < RPI; r++) {
#pragma unroll
            for (int off = 16; off; off >>= 1)
                dot[r] += __shfl_xor_sync(0xffffffffu, dot[r], off);
        }
        if (lane == 0) {
#pragma unroll
            for (int r = 0; r < RPI; r++) red[r][warp] = dot[r];
        }
        __syncthreads();

        float sc[RPI], mnew = m;
#pragma unroll
        for (int r = 0; r < RPI; r++) {
            float v = red[r][0] + red[r][1] + red[r][2] + red[r][3]
                    + red[r][4] + red[r][5] + red[r][6] + red[r][7];
            sc[r] = v;
            mnew = fmaxf(mnew, v);
        }

        float f = __expf(m - mnew);           /* first iter: exp(-inf)=0 */
        ssum *= f;
        c0.x *= f; c0.y *= f; c0.z *= f; c0.w *= f;
        c1.x *= f; c1.y *= f; c1.z *= f; c1.w *= f;
#pragma unroll
        for (int r = 0; r < RPI; r++) {
            float w = __expf(sc[r] - mnew);
            ssum += w;
            float4 a0 = cur[r*(DIM/4) + t], a1 = cur[r*(DIM/4) + t + 256];
            c0.x = fmaf(w, a0.x, c0.x); c0.y = fmaf(w, a0.y, c0.y);
            c0.z = fmaf(w, a0.z, c0.z); c0.w = fmaf(w, a0.w, c0.w);
            c1.x = fmaf(w, a1.x, c1.x); c1.y = fmaf(w, a1.y, c1.y);
            c1.z = fmaf(w, a1.z, c1.z); c1.w = fmaf(w, a1.w, c1.w);
        }
        m = mnew;
        /* top-of-loop __syncthreads guards cur reuse & red rewrite */
    }

    const int pidx = b*NSPLIT + split;
    if (t == 0) { mp[pidx] = m; sp[pidx] = ssum; }
    float4* cpp = (float4*)(cp + (size_t)pidx*DIM);
    cpp[t] = c0; cpp[t + 256] = c1;           /* matches owned-column layout */
}

/* ---------------------------------------------------------------
 * Combine split partials:  cn[b][col] = (1/S) * sum_j exp(m_j-M)*c_j[col]
 * grid (NB, DIM/128), block 128.
 * --------------------------------------------------------------- */
__global__ void __launch_bounds__(128) combine_k(
    const float* __restrict__ mp, const float* __restrict__ sp,
    const float* __restrict__ cp, float* __restrict__ cn)
{
    const int b = blockIdx.x;
    const int t = threadIdx.x;
    __shared__ float fsh[NSPLIT];
    __shared__ float invS_sh;

    float M = -CUDART_INF_F;
#pragma unroll
    for (int j = 0; j < NSPLIT; j++) M = fmaxf(M, mp[b*NSPLIT + j]);
    if (t < NSPLIT) fsh[t] = __expf(mp[b*NSPLIT + t] - M);
    __syncthreads();
    if (t == 0) {
        float S = 0.f;
#pragma unroll
        for (int j = 0; j < NSPLIT; j++) S += sp[b*NSPLIT + j]*fsh[j];
        invS_sh = 1.f/S;
    }
    __syncthreads();
    const float invS = invS_sh;

    const int col = blockIdx.y*128 + t;
    float acc = 0.f;
#pragma unroll 4
    for (int j = 0; j < NSPLIT; j++)
        acc += cp[((size_t)(b*NSPLIT + j))*DIM + col]*fsh[j];
    cn[b*DIM + col] = acc*invS;
}

/* ---------------------------------------------------------------- */
extern "C" void kernel_launch(void* const* d_in, const int* in_sizes, int n_in,
                              void* d_out, int out_size)
{
    const float* cur = (const float*)d_in[0];
    const float* ctx = (const float*)d_in[1];
    const float* Wq  = (const float*)d_in[2];
    const float* bq  = (const float*)d_in[3];
    const float* Wk  = (const float*)d_in[4];
    /* bk (d_in[5]) is provably softmax-invariant: q.bk is constant in l */
    const float* Wv  = (const float*)d_in[6];
    const float* bv  = (const float*)d_in[7];
    float* out = (float*)d_out;

    float *q, *part, *mP, *sP, *cP, *cn;
    cudaGetSymbolAddress((void**)&q,    g_q);
    cudaGetSymbolAddress((void**)&part, g_part);
    cudaGetSymbolAddress((void**)&mP,   g_m);
    cudaGetSymbolAddress((void**)&sP,   g_s);
    cudaGetSymbolAddress((void**)&cP,   g_c);
    cudaGetSymbolAddress((void**)&cn,   g_cn);

    const int attn_smem = 2*RPI*(DIM/4)*(int)sizeof(float4);  /* 64 KB */
    cudaFuncSetAttribute(attn_partial_k,
                         cudaFuncAttributeMaxDynamicSharedMemorySize, attn_smem);

    /* 1-2: q = cur @ Wq + bq */
    gemv_partial_k<<<dim3(DIM/128, ISPLIT), 128>>>(cur, Wq, part);
    reduce_bias_k<<<NB*DIM/256, 256>>>(part, bq, q);

    /* 3: qk partials (reduce+scale fused into attn prologue) */
    qk_partial_k<<<dim3(DIM/8, ASPLIT), 256>>>(q, Wk, part);

    /* 4: streaming online-softmax over context, cp.async pipelined */
    attn_partial_k<<<dim3(NSPLIT, NB), 256, attn_smem>>>(ctx, part, mP, sP, cP);

    /* 5: combine partials -> normalized weighted context cn */
    combine_k<<<dim3(NB, DIM/128), 128>>>(mP, sP, cP, cn);

    /* 6-7: out = cn @ Wv + bv */
    gemv_partial_k<<<dim3(DIM/128, ISPLIT), 128>>>(cn, Wv, part);
    reduce_bias_k<<<NB*DIM/256, 256>>>(part, bv, out);
}

// round 12
// speedup vs baseline: 1.3602x; 1.0707x over previous
#include <cuda_runtime.h>
#include <math_constants.h>

#define DIM    2048
#define NB     16
#define LCTX   4096
#define NSPLIT 64
#define ROWS   (LCTX/NSPLIT)   /* 64 rows per attention split   */
#define RPI    4               /* rows per pipelined tile       */
#define NT     (ROWS/RPI)      /* 16 tiles per block            */
#define ISPLIT 32
#define ICHUNK (DIM/ISPLIT)    /* 64 */
#define FBLK   256             /* fused-kernel grid size        */
#define SCALE  0.02209708691207961f /* 1/sqrt(2048) */

/* -------- scratch ( __device__ globals, no allocation ) -------- */
__device__ float g_q   [NB*DIM];
__device__ float g_qk  [NB*DIM];
__device__ float g_part[ISPLIT*NB*DIM];
__device__ float g_m   [NB*NSPLIT];
__device__ float g_s   [NB*NSPLIT];
__device__ float g_c   [(size_t)NB*NSPLIT*DIM];
__device__ float g_cn  [NB*DIM];

/* -------- self-resetting grid barrier (all blocks co-resident) -- */
__device__ unsigned g_bar_cnt = 0;
__device__ unsigned g_bar_gen = 0;

__device__ __forceinline__ void grid_barrier()
{
    __syncthreads();
    if (threadIdx.x == 0) {
        __threadfence();
        volatile unsigned* genp = &g_bar_gen;
        unsigned my_gen = *genp;
        if (atomicInc(&g_bar_cnt, FBLK - 1) == FBLK - 1) {
            *genp = my_gen + 1;            /* last arriver releases */
        } else {
            while (*genp == my_gen) { __nanosleep(64); }
        }
        __threadfence();
    }
    __syncthreads();
}

/* ---------------- cp.async helpers ---------------- */
__device__ __forceinline__ void cpa16(void* smem_dst, const void* gsrc)
{
    unsigned saddr = (unsigned)__cvta_generic_to_shared(smem_dst);
    asm volatile("cp.async.cg.shared.global [%0], [%1], 16;\n"
                 :: "r"(saddr), "l"(gsrc));
}
__device__ __forceinline__ void cpa_commit()
{ asm volatile("cp.async.commit_group;\n"); }
__device__ __forceinline__ void cpa_wait0()
{ asm volatile("cp.async.wait_group 0;\n"); }

/* ---------------------------------------------------------------
 * GEMV partial phase (device fn): part[k][b][o] += A[b][i]*W[i][o]
 * over i-chunk k.  One block = (o-tile of 256, one k).
 * tasks: (DIM/256) x ISPLIT = 8*32 = 256 = FBLK   (exact fit)
 * --------------------------------------------------------------- */
__device__ __forceinline__ void gemv_partial_phase(
    const float* __restrict__ A, const float* __restrict__ W,
    float* __restrict__ part, float* __restrict__ sm /* >= NB*ICHUNK */)
{
    const int t  = threadIdx.x;
    const int ox = blockIdx.x & 7;            /* 8 o-tiles of 256 */
    const int k  = blockIdx.x >> 3;           /* 32 i-chunks      */
    const int o  = ox*256 + t;
    const int i0 = k*ICHUNK;

    for (int idx = t; idx < NB*ICHUNK; idx += 256) {
        int bb = idx / ICHUNK, ii = idx & (ICHUNK-1);
        sm[idx] = A[bb*DIM + i0 + ii];
    }
    __syncthreads();

    float acc[NB];
#pragma unroll
    for (int b = 0; b < NB; b++) acc[b] = 0.f;

    const float* Wp = W + (size_t)i0*DIM + o;
#pragma unroll 16
    for (int ii = 0; ii < ICHUNK; ii++) {
        float w = Wp[(size_t)ii*DIM];
#pragma unroll
        for (int b = 0; b < NB; b++)
            acc[b] = fmaf(sm[b*ICHUNK + ii], w, acc[b]);
    }

    float* pp = part + ((size_t)k*NB)*DIM + o;
#pragma unroll
    for (int b = 0; b < NB; b++) pp[(size_t)b*DIM] = acc[b];
    __syncthreads();                          /* sm reused by caller */
}

/* reduce ISPLIT partials + bias phase: 32768 elems, 65536 threads */
__device__ __forceinline__ void reduce_bias_phase(
    const float* __restrict__ part, const float* __restrict__ bias,
    float* __restrict__ out)
{
    int idx = blockIdx.x*256 + threadIdx.x;   /* = b*DIM + o */
    if (idx < NB*DIM) {
        int o = idx & (DIM-1);
        float s = bias[o];
#pragma unroll
        for (int k = 0; k < ISPLIT; k++) s += part[(size_t)k*NB*DIM + idx];
        out[idx] = s;
    }
}

/* ===============================================================
 * FUSED PRE kernel: q = cur@Wq+bq ; qk = SCALE*(q@Wk^T)
 * grid FBLK=256 blocks, 256 threads, <=8KB smem, 2 blocks/SM min.
 * =============================================================== */
__global__ void __launch_bounds__(256, 2) fused_pre_k(
    const float* __restrict__ cur, const float* __restrict__ Wq,
    const float* __restrict__ bq,  const float* __restrict__ Wk,
    float* __restrict__ part, float* __restrict__ q,
    float* __restrict__ qk)
{
    __shared__ float sm[NB*128];              /* 8 KB, reused */

    /* A: Wq GEMV partials */
    gemv_partial_phase(cur, Wq, part, sm);
    grid_barrier();

    /* B: reduce + bias -> q */
    reduce_bias_phase(part, bq, q);
    grid_barrier();

    /* C: qk[b][i] = SCALE * sum_a q[b][a]*Wk[i][a]
       warp per row i, 8 warps/block, 256 blocks -> DIM rows exact */
    {
        const int warp = threadIdx.x >> 5, lane = threadIdx.x & 31;
        const int i = blockIdx.x*8 + warp;

        float acc[NB];
#pragma unroll
        for (int b = 0; b < NB; b++) acc[b] = 0.f;

        for (int a0 = 0; a0 < DIM; a0 += 128) {
            __syncthreads();
            for (int idx = threadIdx.x; idx < NB*128; idx += 256) {
                int bb = idx >> 7, aa = idx & 127;
                sm[idx] = q[bb*DIM + a0 + aa];
            }
            __syncthreads();
            const float* wrow = Wk + (size_t)i*DIM + a0;
#pragma unroll
            for (int aa = lane; aa < 128; aa += 32) {
                float wv = wrow[aa];
#pragma unroll
                for (int b = 0; b < NB; b++)
                    acc[b] = fmaf(sm[b*128 + aa], wv, acc[b]);
            }
        }
#pragma unroll
        for (int b = 0; b < NB; b++) {
#pragma unroll
            for (int off = 16; off; off >>= 1)
                acc[b] += __shfl_xor_sync(0xffffffffu, acc[b], off);
        }
        if (lane == 0) {
#pragma unroll
            for (int b = 0; b < NB; b++) qk[b*DIM + i] = acc[b]*SCALE;
        }
    }
}

/* ===============================================================
 * Main streaming kernel: online softmax + weighted context accum,
 * double-buffered cp.async pipeline.  grid (NSPLIT, NB), 256 thr,
 * 64KB dynamic smem.  Thread t owns cols {4t..4t+3, 1024+4t..}.
 * =============================================================== */
__device__ __forceinline__ float dot8(float4 a0, float4 a1, float4 b0, float4 b1)
{
    float d = a0.x*b0.x;
    d = fmaf(a0.y, b0.y, d); d = fmaf(a0.z, b0.z, d); d = fmaf(a0.w, b0.w, d);
    d = fmaf(a1.x, b1.x, d); d = fmaf(a1.y, b1.y, d);
    d = fmaf(a1.z, b1.z, d); d = fmaf(a1.w, b1.w, d);
    return d;
}

__global__ void __launch_bounds__(256) attn_partial_k(
    const float* __restrict__ ctx, const float* __restrict__ qk,
    float* __restrict__ mp, float* __restrict__ sp, float* __restrict__ cp)
{
    extern __shared__ float4 xs[];            /* [2][RPI][DIM/4] = 64 KB */
    __shared__ float red[RPI][8];

    const int b = blockIdx.y, split = blockIdx.x;
    const int t = threadIdx.x;
    const int warp = t >> 5, lane = t & 31;

    const float4* xb = (const float4*)(ctx + ((size_t)b*LCTX + (size_t)split*ROWS)*DIM);
    const float4* qv = (const float4*)(qk + (size_t)b*DIM);
    const float4 qv0 = qv[t], qv1 = qv[t + 256];

    float4 c0 = make_float4(0,0,0,0), c1 = make_float4(0,0,0,0);
    float  m = -CUDART_INF_F, ssum = 0.f;

    /* prologue: stage tile 0 into buffer 0 (2048 float4, 8/thread) */
#pragma unroll
    for (int k = 0; k < 2*RPI; k++) {
        int idx = k*256 + t;
        cpa16(&xs[idx], &xb[idx]);
    }
    cpa_commit();

    for (int tile = 0; tile < NT; tile++) {
        float4* cur = xs + ((tile & 1) ? RPI*(DIM/4) : 0);
        float4* nxt = xs + ((tile & 1) ? 0 : RPI*(DIM/4));

        cpa_wait0();          /* tile data landed                */
        __syncthreads();      /* ..and prev consumers done w/cur */

        if (tile + 1 < NT) {
            const float4* src = xb + (size_t)(tile + 1)*RPI*(DIM/4);
#pragma unroll
            for (int k = 0; k < 2*RPI; k++) {
                int idx = k*256 + t;
                cpa16(&nxt[idx], &src[idx]);
            }
        }
        cpa_commit();

        float dot[RPI];
#pragma unroll
        for (int r = 0; r < RPI; r++)
            dot[r] = dot8(cur[r*(DIM/4) + t], cur[r*(DIM/4) + t + 256], qv0, qv1);
#pragma unroll
        for (int r = 0; r < RPI; r++) {
#pragma unroll
            for (int off = 16; off; off >>= 1)
                dot[r] += __shfl_xor_sync(0xffffffffu, dot[r], off);
        }
        if (lane == 0) {
#pragma unroll
            for (int r = 0; r < RPI; r++) red[r][warp] = dot[r];
        }
        __syncthreads();

        float sc[RPI], mnew = m;
#pragma unroll
        for (int r = 0; r < RPI; r++) {
            float v = red[r][0] + red[r][1] + red[r][2] + red[r][3]
                    + red[r][4] + red[r][5] + red[r][6] + red[r][7];
            sc[r] = v;
            mnew = fmaxf(mnew, v);
        }

        float f = __expf(m - mnew);           /* first iter: exp(-inf)=0 */
        ssum *= f;
        c0.x *= f; c0.y *= f; c0.z *= f; c0.w *= f;
        c1.x *= f; c1.y *= f; c1.z *= f; c1.w *= f;
#pragma unroll
        for (int r = 0; r < RPI; r++) {
            float w = __expf(sc[r] - mnew);
            ssum += w;
            float4 a0 = cur[r*(DIM/4) + t], a1 = cur[r*(DIM/4) + t + 256];
            c0.x = fmaf(w, a0.x, c0.x); c0.y = fmaf(w, a0.y, c0.y);
            c0.z = fmaf(w, a0.z, c0.z); c0.w = fmaf(w, a0.w, c0.w);
            c1.x = fmaf(w, a1.x, c1.x); c1.y = fmaf(w, a1.y, c1.y);
            c1.z = fmaf(w, a1.z, c1.z); c1.w = fmaf(w, a1.w, c1.w);
        }
        m = mnew;
    }

    const int pidx = b*NSPLIT + split;
    if (t == 0) { mp[pidx] = m; sp[pidx] = ssum; }
    float4* cpp = (float4*)(cp + (size_t)pidx*DIM);
    cpp[t] = c0; cpp[t + 256] = c1;
}

/* ===============================================================
 * FUSED POST kernel: combine -> cn ; out = cn@Wv + bv
 * grid FBLK=256 blocks, 256 threads.
 * =============================================================== */
__global__ void __launch_bounds__(256, 2) fused_post_k(
    const float* __restrict__ mp, const float* __restrict__ sp,
    const float* __restrict__ cpart,
    const float* __restrict__ Wv, const float* __restrict__ bv,
    float* __restrict__ part, float* __restrict__ cn,
    float* __restrict__ out)
{
    __shared__ float sm[NB*128];              /* 8 KB, reused */

    /* A: combine split partials -> cn.  tasks: b(16) x colblk(8) = 128 */
    if (blockIdx.x < NB*8) {
        const int b  = blockIdx.x >> 3;
        const int cb = blockIdx.x & 7;
        const int t  = threadIdx.x;

        float M = -CUDART_INF_F;
#pragma unroll
        for (int j = 0; j < NSPLIT; j++) M = fmaxf(M, mp[b*NSPLIT + j]);
        if (t < NSPLIT) sm[t] = __expf(mp[b*NSPLIT + t] - M);
        __syncthreads();
        if (t == 0) {
            float S = 0.f;
#pragma unroll
            for (int j = 0; j < NSPLIT; j++) S += sp[b*NSPLIT + j]*sm[j];
            sm[NSPLIT] = 1.f/S;
        }
        __syncthreads();
        const float invS = sm[NSPLIT];

        const int col = cb*256 + t;
        float acc = 0.f;
#pragma unroll 4
        for (int j = 0; j < NSPLIT; j++)
            acc += cpart[((size_t)(b*NSPLIT + j))*DIM + col]*sm[j];
        cn[b*DIM + col] = acc*invS;
        __syncthreads();
    }
    grid_barrier();

    /* B: Wv GEMV partials */
    gemv_partial_phase(cn, Wv, part, sm);
    grid_barrier();

    /* C: reduce + bias -> out */
    reduce_bias_phase(part, bv, out);
}

/* ---------------------------------------------------------------- */
extern "C" void kernel_launch(void* const* d_in, const int* in_sizes, int n_in,
                              void* d_out, int out_size)
{
    const float* cur = (const float*)d_in[0];
    const float* ctx = (const float*)d_in[1];
    const float* Wq  = (const float*)d_in[2];
    const float* bq  = (const float*)d_in[3];
    const float* Wk  = (const float*)d_in[4];
    /* bk (d_in[5]) is provably softmax-invariant: q.bk is constant in l */
    const float* Wv  = (const float*)d_in[6];
    const float* bv  = (const float*)d_in[7];
    float* out = (float*)d_out;

    float *q, *qkv, *part, *mP, *sP, *cP, *cn;
    cudaGetSymbolAddress((void**)&q,    g_q);
    cudaGetSymbolAddress((void**)&qkv,  g_qk);
    cudaGetSymbolAddress((void**)&part, g_part);
    cudaGetSymbolAddress((void**)&mP,   g_m);
    cudaGetSymbolAddress((void**)&sP,   g_s);
    cudaGetSymbolAddress((void**)&cP,   g_c);
    cudaGetSymbolAddress((void**)&cn,   g_cn);

    const int attn_smem = 2*RPI*(DIM/4)*(int)sizeof(float4);  /* 64 KB */
    cudaFuncSetAttribute(attn_partial_k,
                         cudaFuncAttributeMaxDynamicSharedMemorySize, attn_smem);

    /* 1: q = cur@Wq+bq ; qk = SCALE*(q@Wk^T)   (persistent, 2 grid barriers) */
    fused_pre_k<<<FBLK, 256>>>(cur, Wq, bq, Wk, part, q, qkv);

    /* 2: streaming online-softmax over context, cp.async pipelined */
    attn_partial_k<<<dim3(NSPLIT, NB), 256, attn_smem>>>(ctx, qkv, mP, sP, cP);

    /* 3: combine -> cn ; out = cn@Wv + bv      (persistent, 2 grid barriers) */
    fused_post_k<<<FBLK, 256>>>(mP, sP, cP, Wv, bv, part, cn, out);
}